// round 6
// baseline (speedup 1.0000x reference)
#include <cuda_runtime.h>
#include <cuda_bf16.h>

#define B 4
#define C 128
#define CM 64
#define CO 100
#define HO 128
#define WO 128

typedef unsigned long long u64;

__device__ __forceinline__ u64 pk(float lo, float hi) {
    u64 r; asm("mov.b64 %0, {%1,%2};" : "=l"(r) : "f"(lo), "f"(hi)); return r;
}
__device__ __forceinline__ float2 upk(u64 v) {
    float2 f; asm("mov.b64 {%0,%1}, %2;" : "=f"(f.x), "=f"(f.y) : "l"(v)); return f;
}
#define FMA2(d,a,b) asm("fma.rn.f32x2 %0, %1, %2, %0;" : "+l"(d) : "l"(a), "l"(b))
#define MUL2(d,a,b) asm("mul.rn.f32x2 %0, %1, %2;" : "=l"(d) : "l"(a), "l"(b))

// scratch
__device__ u64   g_wc2[C*CM];         // comp weights [c][m] DUPLICATED (w,w)
__device__ u64   g_we2[CM*9*CO];      // enc weights  [c][tap][o] DUPLICATED (w,w)
__device__ float g_W1[B*CM*64*64];    // conv1x1+SiLU activations
__device__ float g_W2[B*CO*64*64];    // conv3x3+BN logits

// ---------------------------------------------------------------------------
// K0: fold BN scale, transpose, and DUPLICATE weights into (w,w) u64 pairs
// ---------------------------------------------------------------------------
__global__ void k0_prep(const float* __restrict__ cw, const float* __restrict__ cg,
                        const float* __restrict__ ew, const float* __restrict__ eg) {
    int i = blockIdx.x * blockDim.x + threadIdx.x;
    const float s = rsqrtf(1.0f + 1e-5f);
    if (i < C*CM) {
        int c = i >> 6, m = i & 63;
        float v = cw[m*C + c] * (cg[m] * s);
        g_wc2[i] = pk(v, v);
    }
    if (i < CM*9*CO) {
        int c = i / 900, r = i - c*900, t = r / 100, o = r - t*100;
        float v = ew[(o*CM + c)*9 + t] * (eg[o] * s);
        g_we2[i] = pk(v, v);
    }
}

// ---------------------------------------------------------------------------
// K1: 1x1 conv (128->64) + BN bias + SiLU.  Tile 64m x 64px, grid 256.
// x natural px-pairs (float smem, LDS.128); w pre-duplicated pairs.
// Inner c-step: 3 LDS.128 + 8 FFMA2, zero MOVs.
// ---------------------------------------------------------------------------
__global__ __launch_bounds__(256) void k1_comp(const float* __restrict__ X,
                                               const float* __restrict__ cb) {
    __shared__ __align__(16) float xs[16*64];
    __shared__ __align__(16) u64  ws2[16*64];
    int blk = blockIdx.x;
    int b   = blk >> 6;
    int hw0 = (blk & 63) * 64;
    int tid = threadIdx.x, mg = tid >> 4, pxl = (tid & 15) * 4;

    u64 acc[4][2];
#pragma unroll
    for (int o = 0; o < 4; o++) { acc[o][0] = 0ull; acc[o][1] = 0ull; }

    for (int c0 = 0; c0 < C; c0 += 16) {
        __syncthreads();
        {
            int c = tid >> 4, px = (tid & 15) * 4;
            *(float4*)&xs[c*64 + px] =
                *(const float4*)&X[(b*C + c0 + c)*4096 + hw0 + px];
            ((ulonglong2*)ws2)[tid]       = ((const ulonglong2*)&g_we2[0])[0], // placeholder no-op avoided below
            ((ulonglong2*)ws2)[tid]       = ((const ulonglong2*)&g_wc2[c0*64])[tid];
            ((ulonglong2*)ws2)[tid + 256] = ((const ulonglong2*)&g_wc2[c0*64])[tid + 256];
        }
        __syncthreads();
#pragma unroll
        for (int c = 0; c < 16; c++) {
            ulonglong2 xv = *(const ulonglong2*)&xs[c*64 + pxl];       // (x0,x1),(x2,x3)
            ulonglong2 wA = *(const ulonglong2*)&ws2[c*64 + mg*4];     // (w0,w0),(w1,w1)
            ulonglong2 wB = *(const ulonglong2*)&ws2[c*64 + mg*4 + 2]; // (w2,w2),(w3,w3)
            FMA2(acc[0][0], wA.x, xv.x); FMA2(acc[0][1], wA.x, xv.y);
            FMA2(acc[1][0], wA.y, xv.x); FMA2(acc[1][1], wA.y, xv.y);
            FMA2(acc[2][0], wB.x, xv.x); FMA2(acc[2][1], wB.x, xv.y);
            FMA2(acc[3][0], wB.y, xv.x); FMA2(acc[3][1], wB.y, xv.y);
        }
    }
#pragma unroll
    for (int o = 0; o < 4; o++) {
        int m = mg*4 + o;
        float bias = cb[m];
        float2 f0 = upk(acc[o][0]), f1 = upk(acc[o][1]);
        float z0 = f0.x + bias, z1 = f0.y + bias, z2 = f1.x + bias, z3 = f1.y + bias;
        z0 /= 1.f + __expf(-z0); z1 /= 1.f + __expf(-z1);
        z2 /= 1.f + __expf(-z2); z3 /= 1.f + __expf(-z3);
        *(float4*)&g_W1[(b*CM + m)*4096 + hw0 + pxl] = make_float4(z0, z1, z2, z3);
    }
}

// ---------------------------------------------------------------------------
// K2: 3x3 conv (64->100) + BN bias.  Tile 100o x (4x8)px, grid 512.
// x path identical to the proven 105us version (float smem, E/O pairs);
// w path: pre-duplicated pairs -> per tap 2 LDS.128 + 8 FFMA2, zero MOVs.
// c-chunk 4 (smem: 28.8KB w + 1.2KB x, 4 blocks/SM fits).
// ---------------------------------------------------------------------------
__global__ __launch_bounds__(200, 4) void k2_enc(const float* __restrict__ eb) {
    __shared__ __align__(16) float xs[4*6*12];   // [c][6 rows][pitch 12]
    __shared__ __align__(16) u64  ws2[4*900];    // [c][9 taps][100 o] dup pairs
    int blk  = blockIdx.x;
    int b    = blk >> 7;
    int tile = blk & 127;
    int y0   = (tile >> 3)*4, x0 = (tile & 7)*8;
    int tid  = threadIdx.x;
    int og   = tid >> 3, pg = tid & 7;
    int prow = pg >> 1, pcol = (pg & 1)*4;

    u64 acc[4][2];
#pragma unroll
    for (int o = 0; o < 4; o++) { acc[o][0] = 0ull; acc[o][1] = 0ull; }

    for (int c0 = 0; c0 < CM; c0 += 4) {
        __syncthreads();
        for (int k = tid; k < 240; k += 200) {
            int c = k / 60, p = k - c*60, r = p / 10, cl = p - r*10;
            int y = y0 + r - 1, x = x0 + cl - 1;
            float v = 0.f;
            if ((unsigned)y < 64u && (unsigned)x < 64u)
                v = g_W1[(b*CM + c0 + c)*4096 + y*64 + x];
            xs[c*72 + r*12 + cl] = v;
        }
        {
            const ulonglong2* src = (const ulonglong2*)&g_we2[c0*900];
            ulonglong2* dst = (ulonglong2*)ws2;
#pragma unroll
            for (int j = 0; j < 9; j++) dst[tid + j*200] = src[tid + j*200];
        }
        __syncthreads();

#pragma unroll
        for (int c = 0; c < 4; c++) {
#pragma unroll
            for (int ti = 0; ti < 3; ti++) {
                const float* rb = &xs[c*72 + (prow + ti)*12 + pcol];
                u64 E0 = *(const u64*)rb;          // (x0,x1)
                u64 E1 = *(const u64*)(rb + 2);    // (x2,x3)
                u64 E2 = *(const u64*)(rb + 4);    // (x4,x5)
                float2 f0 = upk(E0), f1 = upk(E1), f2 = upk(E2);
                u64 O0 = pk(f0.y, f1.x);           // (x1,x2)
                u64 O1 = pk(f1.y, f2.x);           // (x3,x4)
#pragma unroll
                for (int tj = 0; tj < 3; tj++) {
                    u64 xa = (tj == 0) ? E0 : (tj == 1) ? O0 : E1;
                    u64 xb = (tj == 0) ? E1 : (tj == 1) ? O1 : E2;
                    const u64* wp = &ws2[(c*9 + ti*3 + tj)*100 + og*4];
                    ulonglong2 wA = *(const ulonglong2*)wp;
                    ulonglong2 wB = *(const ulonglong2*)(wp + 2);
                    FMA2(acc[0][0], wA.x, xa); FMA2(acc[0][1], wA.x, xb);
                    FMA2(acc[1][0], wA.y, xa); FMA2(acc[1][1], wA.y, xb);
                    FMA2(acc[2][0], wB.x, xa); FMA2(acc[2][1], wB.x, xb);
                    FMA2(acc[3][0], wB.y, xa); FMA2(acc[3][1], wB.y, xb);
                }
            }
        }
    }
    int rowbase = (y0 + prow)*64 + x0 + pcol;
#pragma unroll
    for (int o = 0; o < 4; o++) {
        int oo = og*4 + o;
        float bias = eb[oo];
        float2 f0 = upk(acc[o][0]), f1 = upk(acc[o][1]);
        *(float4*)&g_W2[(b*CO + oo)*4096 + rowbase] =
            make_float4(f0.x + bias, f0.y + bias, f1.x + bias, f1.y + bias);
    }
}

// ---------------------------------------------------------------------------
// K3: pixel-shuffle + softmax(25) + CARAFE combine, fused.
// Subpixel-split: 256 thr = 128 px x 2 s-groups; each thread keeps only its
// subpixel PAIR's 25 packed weights (50 regs) -> 3 blocks/SM instead of 4,
// ~24 warps/SM.  X staged duplicated (v,v): per tap 1 LDS.64 + 1 FFMA2 per
// channel, 4 independent chains, zero MOVs.
// ---------------------------------------------------------------------------
__global__ __launch_bounds__(256, 3) void k3_carafe(const float* __restrict__ X,
                                                    float* __restrict__ out) {
    __shared__ __align__(16) u64 xsd[4*240];   // [4 ch][12 rows][20 cols] dup
    int blk    = blockIdx.x;
    int cq     = blk >> 7;          // channel quarter (32 ch)
    int tileid = blk & 127;
    int b  = tileid >> 5;
    int t  = tileid & 31;
    int ty = t >> 2, tx = t & 3;
    int tid  = threadIdx.x;
    int sg   = tid >> 7;            // subpixel group: 0 -> (s0,s1), 1 -> (s2,s3)
    int ptid = tid & 127;
    int py   = ptid >> 4, pxl = ptid & 15;
    int y0g  = ty*8 + py, x0g = tx*16 + pxl;

    // softmax over 25 taps for this thread's subpixel pair
    u64 w[25];
    {
        const float* base = g_W2 + (size_t)b*CO*4096 + y0g*64 + x0g;
        int s = sg*2;
        float sum0 = 0.f, sum1 = 0.f;
#pragma unroll
        for (int k = 0; k < 25; k++) {
            float e0 = __expf(base[(k*4 + s    )*4096]); sum0 += e0;
            float e1 = __expf(base[(k*4 + s + 1)*4096]); sum1 += e1;
            w[k] = pk(e0, e1);
        }
        u64 inv = pk(1.0f/sum0, 1.0f/sum1);
#pragma unroll
        for (int k = 0; k < 25; k++) MUL2(w[k], w[k], inv);
    }

    int cbase = cq*32;
    int ybase = ty*8 - 2, xbase = tx*16 - 2;
    for (int c0 = 0; c0 < 32; c0 += 4) {
        __syncthreads();
        for (int k = tid; k < 960; k += 256) {
            int c = k / 240, p = k - c*240, r = p / 20, cl = p - r*20;
            int y = ybase + r, x = xbase + cl;
            float v = 0.f;
            if ((unsigned)y < 64u && (unsigned)x < 64u)
                v = X[((b*C + cbase + c0 + c)*64 + y)*64 + x];
            *(float2*)&xsd[k] = make_float2(v, v);
        }
        __syncthreads();
        u64 a0 = 0ull, a1 = 0ull, a2 = 0ull, a3 = 0ull;
        const u64* xp = &xsd[py*20 + pxl];
#pragma unroll
        for (int i = 0; i < 5; i++)
#pragma unroll
            for (int j = 0; j < 5; j++) {
                int off = i*20 + j;
                u64 wk = w[i*5 + j];
                FMA2(a0, wk, xp[off]);
                FMA2(a1, wk, xp[off + 240]);
                FMA2(a2, wk, xp[off + 480]);
                FMA2(a3, wk, xp[off + 720]);
            }
        size_t ob = ((size_t)(b*C + cbase + c0)*HO + 2*y0g + sg)*WO + 2*x0g;
        *(float2*)&out[ob]                      = upk(a0);
        *(float2*)&out[ob +   (size_t)HO*WO]    = upk(a1);
        *(float2*)&out[ob + 2*(size_t)HO*WO]    = upk(a2);
        *(float2*)&out[ob + 3*(size_t)HO*WO]    = upk(a3);
    }
}

// ---------------------------------------------------------------------------
extern "C" void kernel_launch(void* const* d_in, const int* in_sizes, int n_in,
                              void* d_out, int out_size) {
    const float* X      = (const float*)d_in[0];
    const float* comp_w = (const float*)d_in[1];
    const float* comp_g = (const float*)d_in[2];
    const float* comp_b = (const float*)d_in[3];
    const float* enc_w  = (const float*)d_in[4];
    const float* enc_g  = (const float*)d_in[5];
    const float* enc_b  = (const float*)d_in[6];
    float* out = (float*)d_out;

    k0_prep  <<<225, 256>>>(comp_w, comp_g, enc_w, enc_g);
    k1_comp  <<<256, 256>>>(X, comp_b);
    k2_enc   <<<512, 200>>>(enc_b);
    k3_carafe<<<512, 256>>>(X, out);
}

// round 7
// speedup vs baseline: 1.4228x; 1.4228x over previous
#include <cuda_runtime.h>
#include <cuda_bf16.h>

#define B 4
#define C 128
#define CM 64
#define CO 100
#define HO 128
#define WO 128

typedef unsigned long long u64;

__device__ __forceinline__ u64 pk(float lo, float hi) {
    u64 r; asm("mov.b64 %0, {%1,%2};" : "=l"(r) : "f"(lo), "f"(hi)); return r;
}
__device__ __forceinline__ float2 upk(u64 v) {
    float2 f; asm("mov.b64 {%0,%1}, %2;" : "=f"(f.x), "=f"(f.y) : "l"(v)); return f;
}
#define FMA2(d,a,b) asm("fma.rn.f32x2 %0, %1, %2, %0;" : "+l"(d) : "l"(a), "l"(b))
#define MUL2(d,a,b) asm("mul.rn.f32x2 %0, %1, %2;" : "=l"(d) : "l"(a), "l"(b))

// scratch
__device__ float g_wc[C*CM];          // comp weights [c][m], BN-scaled
__device__ float g_we[CM*9*CO];       // enc weights  [c][tap][o], BN-scaled
__device__ float g_W1[B*CM*64*64];    // conv1x1+SiLU activations
__device__ float g_W2[B*CO*64*64];    // conv3x3+BN logits

// ---------------------------------------------------------------------------
// K0: fold BN scale into weights and transpose  (R2 version)
// ---------------------------------------------------------------------------
__global__ void k0_prep(const float* __restrict__ cw, const float* __restrict__ cg,
                        const float* __restrict__ ew, const float* __restrict__ eg) {
    int i = blockIdx.x * blockDim.x + threadIdx.x;
    const float s = rsqrtf(1.0f + 1e-5f);
    if (i < C*CM) {
        int c = i >> 6, m = i & 63;
        g_wc[i] = cw[m*C + c] * (cg[m] * s);
    }
    if (i < CM*9*CO) {
        int c = i / 900, r = i - c*900, t = r / 100, o = r - t*100;
        g_we[i] = ew[(o*CM + c)*9 + t] * (eg[o] * s);
    }
}

// ---------------------------------------------------------------------------
// K1: 1x1 conv (128->64) + BN bias + SiLU  (exact R2/105us version)
// ---------------------------------------------------------------------------
__global__ __launch_bounds__(256) void k1_comp(const float* __restrict__ X,
                                               const float* __restrict__ cb) {
    __shared__ float xs[16*64];
    __shared__ float ws[16*64];
    int blk = blockIdx.x;
    int b   = blk >> 6;
    int hw0 = (blk & 63) * 64;
    int tid = threadIdx.x, mg = tid >> 4, pxl = (tid & 15) * 4;

    u64 acc[4][2];
#pragma unroll
    for (int o = 0; o < 4; o++) { acc[o][0] = 0ull; acc[o][1] = 0ull; }

    for (int c0 = 0; c0 < C; c0 += 16) {
        __syncthreads();
        {
            int c = tid >> 4, px = (tid & 15) * 4;
            *(float4*)&xs[c*64 + px] =
                *(const float4*)&X[(b*C + c0 + c)*4096 + hw0 + px];
            *(float4*)&ws[tid*4] = *(const float4*)&g_wc[c0*64 + tid*4];
        }
        __syncthreads();
#pragma unroll
        for (int c = 0; c < 16; c++) {
            float4 w = *(const float4*)&ws[c*64 + mg*4];
            u64 w0 = pk(w.x,w.x), w1 = pk(w.y,w.y), w2 = pk(w.z,w.z), w3 = pk(w.w,w.w);
            u64 xa = *(const u64*)&xs[c*64 + pxl];
            u64 xb = *(const u64*)&xs[c*64 + pxl + 2];
            FMA2(acc[0][0], w0, xa); FMA2(acc[0][1], w0, xb);
            FMA2(acc[1][0], w1, xa); FMA2(acc[1][1], w1, xb);
            FMA2(acc[2][0], w2, xa); FMA2(acc[2][1], w2, xb);
            FMA2(acc[3][0], w3, xa); FMA2(acc[3][1], w3, xb);
        }
    }
#pragma unroll
    for (int o = 0; o < 4; o++) {
        int m = mg*4 + o;
        float bias = cb[m];
        float* dst = &g_W1[(b*CM + m)*4096 + hw0 + pxl];
#pragma unroll
        for (int j = 0; j < 2; j++) {
            float2 v = upk(acc[o][j]);
            float z0 = v.x + bias, z1 = v.y + bias;
            float y0 = z0 / (1.0f + __expf(-z0));
            float y1 = z1 / (1.0f + __expf(-z1));
            *(float2*)(dst + j*2) = make_float2(y0, y1);
        }
    }
}

// ---------------------------------------------------------------------------
// K2 v3: 3x3 conv (64->100) + BN bias.  Tile 100o x 64px (8x8), grid 256.
// Block 200 = 25 og(4o) x 8 pg(one 8-px row each).
// Acc pairs along o: w natural pairs (1 LDS.128 -> 2 u64 pairs).
// x staged DUPLICATED (v,v) in smem: per tap-row 5 LDS.128, broadcast across
// og; 8 pg rows hit disjoint banks (pitch 80B).  Inner loop: zero MOVs,
// 144 FFMA2 + 24 LDS.128 per channel per thread.
// ---------------------------------------------------------------------------
__global__ __launch_bounds__(200, 4) void k2_enc(const float* __restrict__ eb) {
    __shared__ __align__(16) u64  xsd[4*100];    // [c][10 rows][10 cols] dup
    __shared__ __align__(16) float ws[4*900];    // [c][9 taps][100 o]
    int blk  = blockIdx.x;
    int b    = blk >> 6;
    int tile = blk & 63;
    int y0   = (tile >> 3)*8, x0 = (tile & 7)*8;
    int tid  = threadIdx.x;
    int og   = tid >> 3, pg = tid & 7;

    u64 accA[8], accB[8];                        // (o0,o1),(o2,o3) per px
#pragma unroll
    for (int p = 0; p < 8; p++) { accA[p] = 0ull; accB[p] = 0ull; }

    for (int c0 = 0; c0 < CM; c0 += 4) {
        __syncthreads();
        // stage x window 10x10 per channel, duplicated
#pragma unroll
        for (int j = 0; j < 2; j++) {
            int k = tid + j*200;
            int c = k / 100, p = k - c*100, r = p / 10, cl = p - r*10;
            int y = y0 + r - 1, x = x0 + cl - 1;
            float v = 0.f;
            if ((unsigned)y < 64u && (unsigned)x < 64u)
                v = g_W1[(b*CM + c0 + c)*4096 + y*64 + x];
            *(float2*)&xsd[c*100 + r*10 + cl] = make_float2(v, v);
        }
        // stage weights: 3600 floats = 900 float4
        {
            const float4* src = (const float4*)&g_we[c0*900];
            float4* dst = (float4*)ws;
#pragma unroll
            for (int j = 0; j < 5; j++) {
                int idx = tid + j*200;
                if (idx < 900) dst[idx] = src[idx];
            }
        }
        __syncthreads();

#pragma unroll
        for (int c = 0; c < 4; c++) {
#pragma unroll
            for (int ti = 0; ti < 3; ti++) {
                const u64* rb = &xsd[c*100 + (pg + ti)*10];
                ulonglong2 xA = *(const ulonglong2*)(rb);
                ulonglong2 xB = *(const ulonglong2*)(rb + 2);
                ulonglong2 xC = *(const ulonglong2*)(rb + 4);
                ulonglong2 xD = *(const ulonglong2*)(rb + 6);
                ulonglong2 xE = *(const ulonglong2*)(rb + 8);
                u64 xr[10] = {xA.x,xA.y, xB.x,xB.y, xC.x,xC.y,
                              xD.x,xD.y, xE.x,xE.y};
#pragma unroll
                for (int tj = 0; tj < 3; tj++) {
                    ulonglong2 wp = *(const ulonglong2*)&ws[(c*9 + ti*3 + tj)*100 + og*4];
#pragma unroll
                    for (int p = 0; p < 8; p++) {
                        FMA2(accA[p], wp.x, xr[p + tj]);
                        FMA2(accB[p], wp.y, xr[p + tj]);
                    }
                }
            }
        }
    }
    // epilogue: transpose pairs -> 4 o-rows of 8 px
    float4 bias = *(const float4*)&eb[og*4];
    float r0[8], r1[8], r2[8], r3[8];
#pragma unroll
    for (int p = 0; p < 8; p++) {
        float2 f01 = upk(accA[p]), f23 = upk(accB[p]);
        r0[p] = f01.x + bias.x; r1[p] = f01.y + bias.y;
        r2[p] = f23.x + bias.z; r3[p] = f23.y + bias.w;
    }
    float* d = &g_W2[(b*CO + og*4)*4096 + (y0 + pg)*64 + x0];
    *(float4*)(d)            = make_float4(r0[0],r0[1],r0[2],r0[3]);
    *(float4*)(d + 4)        = make_float4(r0[4],r0[5],r0[6],r0[7]);
    *(float4*)(d + 4096)     = make_float4(r1[0],r1[1],r1[2],r1[3]);
    *(float4*)(d + 4100)     = make_float4(r1[4],r1[5],r1[6],r1[7]);
    *(float4*)(d + 8192)     = make_float4(r2[0],r2[1],r2[2],r2[3]);
    *(float4*)(d + 8196)     = make_float4(r2[4],r2[5],r2[6],r2[7]);
    *(float4*)(d + 12288)    = make_float4(r3[0],r3[1],r3[2],r3[3]);
    *(float4*)(d + 12292)    = make_float4(r3[4],r3[5],r3[6],r3[7]);
}

// ---------------------------------------------------------------------------
// K3: pixel-shuffle + softmax(25) + CARAFE combine  (exact R2/30.6us version)
// ---------------------------------------------------------------------------
__global__ __launch_bounds__(128, 4) void k3_carafe(const float* __restrict__ X,
                                                    float* __restrict__ out) {
    __shared__ float xs[4*240];    // [c][12 rows][pitch 20]
    int blk    = blockIdx.x;
    int cq     = blk >> 7;          // channel quarter 0..3
    int tileid = blk & 127;
    int b  = tileid >> 5;
    int t  = tileid & 31;
    int ty = t >> 2, tx = t & 3;
    int tid = threadIdx.x;
    int py  = tid >> 4, pxl = tid & 15;
    int y0g = ty*8 + py, x0g = tx*16 + pxl;

    u64 w01[25], w23[25];
    {
        const float* base = g_W2 + (size_t)b*CO*4096 + y0g*64 + x0g;
        float s0 = 0.f, s1 = 0.f, s2 = 0.f, s3 = 0.f;
#pragma unroll
        for (int k = 0; k < 25; k++) {
            float e0 = __expf(base[(k*4 + 0)*4096]); s0 += e0;
            float e1 = __expf(base[(k*4 + 1)*4096]); s1 += e1;
            w01[k] = pk(e0, e1);
            float e2 = __expf(base[(k*4 + 2)*4096]); s2 += e2;
            float e3 = __expf(base[(k*4 + 3)*4096]); s3 += e3;
            w23[k] = pk(e2, e3);
        }
        u64 i01 = pk(1.0f/s0, 1.0f/s1);
        u64 i23 = pk(1.0f/s2, 1.0f/s3);
#pragma unroll
        for (int k = 0; k < 25; k++) {
            MUL2(w01[k], w01[k], i01);
            MUL2(w23[k], w23[k], i23);
        }
    }

    int cbase = cq*32;
    int ybase = ty*8 - 2, xbase = tx*16 - 2;
    for (int c0 = 0; c0 < 32; c0 += 4) {
        __syncthreads();
        for (int k = tid; k < 960; k += 128) {
            int c = k / 240, p = k - c*240, r = p / 20, cl = p - r*20;
            int y = ybase + r, x = xbase + cl;
            float v = 0.f;
            if ((unsigned)y < 64u && (unsigned)x < 64u)
                v = X[((b*C + cbase + c0 + c)*64 + y)*64 + x];
            xs[c*240 + r*20 + cl] = v;
        }
        __syncthreads();
#pragma unroll
        for (int c = 0; c < 4; c++) {
            u64 a01 = 0ull, a23 = 0ull;
            const float* xp = &xs[c*240 + py*20 + pxl];
#pragma unroll
            for (int i = 0; i < 5; i++)
#pragma unroll
                for (int j = 0; j < 5; j++) {
                    float xv = xp[i*20 + j];
                    u64 xx = pk(xv, xv);
                    int kk = i*5 + j;
                    FMA2(a01, w01[kk], xx);
                    FMA2(a23, w23[kk], xx);
                }
            int ch = cbase + c0 + c;
            size_t ob = ((size_t)(b*C + ch)*HO + 2*y0g)*WO + 2*x0g;
            float2 top = upk(a01), bot = upk(a23);
            *(float2*)&out[ob]      = top;
            *(float2*)&out[ob + WO] = bot;
        }
    }
}

// ---------------------------------------------------------------------------
extern "C" void kernel_launch(void* const* d_in, const int* in_sizes, int n_in,
                              void* d_out, int out_size) {
    const float* X      = (const float*)d_in[0];
    const float* comp_w = (const float*)d_in[1];
    const float* comp_g = (const float*)d_in[2];
    const float* comp_b = (const float*)d_in[3];
    const float* enc_w  = (const float*)d_in[4];
    const float* enc_g  = (const float*)d_in[5];
    const float* enc_b  = (const float*)d_in[6];
    float* out = (float*)d_out;

    k0_prep  <<<225, 256>>>(comp_w, comp_g, enc_w, enc_g);
    k1_comp  <<<256, 256>>>(X, comp_b);
    k2_enc   <<<256, 200>>>(enc_b);
    k3_carafe<<<512, 128>>>(X, out);
}

// round 11
// speedup vs baseline: 1.9497x; 1.3703x over previous
#include <cuda_runtime.h>
#include <cuda_bf16.h>
#include <cstdint>

#define B 4
#define C 128
#define CM 64
#define CO 100
#define HO 128
#define WO 128

typedef unsigned long long u64;

// ---------------- packed f32x2 helpers (k1/k3 scalar paths) ----------------
__device__ __forceinline__ u64 pk(float lo, float hi) {
    u64 r; asm("mov.b64 %0, {%1,%2};" : "=l"(r) : "f"(lo), "f"(hi)); return r;
}
__device__ __forceinline__ float2 upk(u64 v) {
    float2 f; asm("mov.b64 {%0,%1}, %2;" : "=f"(f.x), "=f"(f.y) : "l"(v)); return f;
}
#define FMA2(d,a,b) asm("fma.rn.f32x2 %0, %1, %2, %0;" : "+l"(d) : "l"(a), "l"(b))
#define MUL2(d,a,b) asm("mul.rn.f32x2 %0, %1, %2;" : "=l"(d) : "l"(a), "l"(b))

__device__ __forceinline__ float tf32r(float x) {
    float y; asm("cvt.rna.tf32.f32 %0, %1;" : "=f"(y) : "f"(x)); return y;
}

// warp-level tf32 MMA (arch-portable PTX, works on bare sm_103 target)
__device__ __forceinline__ void mma_tf32(float* d, uint32_t a0, uint32_t a1,
                                         uint32_t a2, uint32_t a3,
                                         uint32_t b0, uint32_t b1) {
    asm volatile(
        "mma.sync.aligned.m16n8k8.row.col.f32.tf32.tf32.f32 "
        "{%0,%1,%2,%3}, {%4,%5,%6,%7}, {%8,%9}, {%0,%1,%2,%3};"
        : "+f"(d[0]), "+f"(d[1]), "+f"(d[2]), "+f"(d[3])
        : "r"(a0), "r"(a1), "r"(a2), "r"(a3), "r"(b0), "r"(b1));
}

// ---------------- scratch ----------------
__device__ float g_wc[C*CM];            // comp weights [c][m], BN-scaled
__device__ float g_weB[18*112*32];      // enc weights [chunk][112 o][32 c], tf32
__device__ float g_W1T[B*4096*CM];      // conv1x1+SiLU, px-major, tf32-rounded
__device__ float g_W2[B*CO*4096];       // conv3x3+BN logits

// ---------------------------------------------------------------------------
// K0: fold BN scale; build k1 weights + padded tf32 B chunks for k2
// ---------------------------------------------------------------------------
__global__ void k0_prep(const float* __restrict__ cw, const float* __restrict__ cg,
                        const float* __restrict__ ew, const float* __restrict__ eg) {
    int i = blockIdx.x * blockDim.x + threadIdx.x;
    const float s = rsqrtf(1.0f + 1e-5f);
    if (i < C*CM) {
        int c = i >> 6, m = i & 63;
        g_wc[i] = cw[m*C + c] * (cg[m] * s);
    }
    if (i < 18*112*32) {
        int chunk = i / 3584;
        int r     = i - chunk*3584;
        int o     = r >> 5, ck = r & 31;
        int t     = chunk >> 1, ch = chunk & 1;
        float v = 0.f;
        if (o < 100) {
            int c = ch*32 + ck;
            v = tf32r(ew[(o*CM + c)*9 + t] * (eg[o] * s));
        }
        g_weB[i] = v;
    }
}

// ---------------------------------------------------------------------------
// K1: 1x1 conv (128->64) + BN bias + SiLU -> W1T [b][px][c], tf32-rounded
// ---------------------------------------------------------------------------
__global__ __launch_bounds__(256) void k1_comp(const float* __restrict__ X,
                                               const float* __restrict__ cb) {
    __shared__ float xs[16*64];
    __shared__ float ws[16*64];
    int blk = blockIdx.x;
    int b   = blk >> 6;
    int hw0 = (blk & 63) * 64;
    int tid = threadIdx.x, mg = tid >> 4, pxl = (tid & 15) * 4;

    u64 acc[4][2];
#pragma unroll
    for (int o = 0; o < 4; o++) { acc[o][0] = 0ull; acc[o][1] = 0ull; }

    for (int c0 = 0; c0 < C; c0 += 16) {
        __syncthreads();
        {
            int c = tid >> 4, px = (tid & 15) * 4;
            *(float4*)&xs[c*64 + px] =
                *(const float4*)&X[(b*C + c0 + c)*4096 + hw0 + px];
            *(float4*)&ws[tid*4] = *(const float4*)&g_wc[c0*64 + tid*4];
        }
        __syncthreads();
#pragma unroll
        for (int c = 0; c < 16; c++) {
            float4 w = *(const float4*)&ws[c*64 + mg*4];
            u64 w0 = pk(w.x,w.x), w1 = pk(w.y,w.y), w2 = pk(w.z,w.z), w3 = pk(w.w,w.w);
            u64 xa = *(const u64*)&xs[c*64 + pxl];
            u64 xb = *(const u64*)&xs[c*64 + pxl + 2];
            FMA2(acc[0][0], w0, xa); FMA2(acc[0][1], w0, xb);
            FMA2(acc[1][0], w1, xa); FMA2(acc[1][1], w1, xb);
            FMA2(acc[2][0], w2, xa); FMA2(acc[2][1], w2, xb);
            FMA2(acc[3][0], w3, xa); FMA2(acc[3][1], w3, xb);
        }
    }
    float vals[4][4];
#pragma unroll
    for (int o = 0; o < 4; o++) {
        float bias = cb[mg*4 + o];
#pragma unroll
        for (int j = 0; j < 2; j++) {
            float2 v = upk(acc[o][j]);
            float z0 = v.x + bias, z1 = v.y + bias;
            vals[o][j*2]   = tf32r(z0 / (1.0f + __expf(-z0)));
            vals[o][j*2+1] = tf32r(z1 / (1.0f + __expf(-z1)));
        }
    }
#pragma unroll
    for (int p = 0; p < 4; p++) {
        int px = hw0 + pxl + p;
        *(float4*)&g_W1T[((b*4096 + px) << 6) + mg*4] =
            make_float4(vals[0][p], vals[1][p], vals[2][p], vals[3][p]);
    }
}

// ---------------------------------------------------------------------------
// K2: 3x3 conv (64->100) + BN bias via warp-level tf32 MMA (m16n8k8).
// Per block (256 thr, grid 256): D = 64 px (one image row) x 112 o (pad),
// K = 9 taps x 64 c in 18 chunks of 32.  A = im2col with explicit zero-pad;
// B = pre-padded weights.  smem pitch 36 words -> conflict-free frag loads.
// Warp w: m-tile = w>>1 (16 px), o-half = w&1 (56 o = 7 n-tiles).
// ---------------------------------------------------------------------------
__global__ __launch_bounds__(256) void k2_enc(const float* __restrict__ eb) {
    __shared__ float As[64*36];     // [px][32k] pitch 36
    __shared__ float Bs[112*36];    // [o][32k]  pitch 36
    int blk = blockIdx.x, b = blk >> 6, y = blk & 63;
    int tid = threadIdx.x, wid = tid >> 5, lane = tid & 31;
    int mt = wid >> 1, half = wid & 1;
    int px0 = mt*16;
    int arow = lane >> 2, acol = lane & 3;

    float d[7][4];
#pragma unroll
    for (int nt = 0; nt < 7; nt++)
#pragma unroll
        for (int j = 0; j < 4; j++) d[nt][j] = 0.f;

    int spx = tid >> 2, sq = tid & 3;          // A staging coords

    for (int t = 0; t < 9; t++) {
        int ti = t/3 - 1, tj = t%3 - 1;
        int yy = y + ti;
        int xx = spx + tj;
        bool valid = ((unsigned)yy < 64u) && ((unsigned)xx < 64u);
        const float4* asrc = (const float4*)
            &g_W1T[((b*4096 + yy*64 + xx) << 6) + sq*8];
        for (int ch = 0; ch < 2; ch++) {
            __syncthreads();
            {   // stage A: 64 px x 32 c
                float4 v0, v1;
                if (valid) { v0 = asrc[ch*8]; v1 = asrc[ch*8 + 1]; }
                else { v0 = make_float4(0,0,0,0); v1 = v0; }
                float* dst = &As[spx*36 + sq*8];
                *(float2*)(dst)     = make_float2(v0.x, v0.y);
                *(float2*)(dst + 2) = make_float2(v0.z, v0.w);
                *(float2*)(dst + 4) = make_float2(v1.x, v1.y);
                *(float2*)(dst + 6) = make_float2(v1.z, v1.w);
            }
            {   // stage B: 112 o x 32 c (896 float4)
                const float4* src = (const float4*)&g_weB[(t*2 + ch)*3584];
                for (int idx = tid; idx < 896; idx += 256) {
                    float4 v = src[idx];
                    int o = idx >> 3, q = idx & 7;
                    float* dst = &Bs[o*36 + q*4];
                    *(float2*)(dst)     = make_float2(v.x, v.y);
                    *(float2*)(dst + 2) = make_float2(v.z, v.w);
                }
            }
            __syncthreads();
#pragma unroll
            for (int kt = 0; kt < 4; kt++) {
                const float* ab = &As[(px0 + arow)*36 + kt*8 + acol];
                uint32_t a0 = __float_as_uint(ab[0]);
                uint32_t a1 = __float_as_uint(ab[8*36]);
                uint32_t a2 = __float_as_uint(ab[4]);
                uint32_t a3 = __float_as_uint(ab[8*36 + 4]);
#pragma unroll
                for (int nt = 0; nt < 7; nt++) {
                    const float* bb = &Bs[(half*56 + nt*8 + arow)*36 + kt*8 + acol];
                    uint32_t b0 = __float_as_uint(bb[0]);
                    uint32_t b1 = __float_as_uint(bb[4]);
                    mma_tf32(d[nt], a0, a1, a2, a3, b0, b1);
                }
            }
        }
    }

    // epilogue: d0:(pxA,o) d1:(pxA,o+1) d2:(pxB,o) d3:(pxB,o+1)
    int pxA = y*64 + px0 + arow;
    int pxB = pxA + 8;
#pragma unroll
    for (int nt = 0; nt < 7; nt++) {
        int o = half*56 + nt*8 + acol*2;
        if (o < 100) {
            float bias = eb[o];
            float* base = &g_W2[(b*CO + o)*4096];
            base[pxA] = d[nt][0] + bias;
            base[pxB] = d[nt][2] + bias;
        }
        if (o + 1 < 100) {
            float bias = eb[o + 1];
            float* base = &g_W2[(b*CO + o + 1)*4096];
            base[pxA] = d[nt][1] + bias;
            base[pxB] = d[nt][3] + bias;
        }
    }
}

// ---------------------------------------------------------------------------
// K3: pixel-shuffle + softmax(25) + CARAFE combine  (proven 30.6us version)
// ---------------------------------------------------------------------------
__global__ __launch_bounds__(128, 4) void k3_carafe(const float* __restrict__ X,
                                                    float* __restrict__ out) {
    __shared__ float xs[4*240];
    int blk    = blockIdx.x;
    int cq     = blk >> 7;
    int tileid = blk & 127;
    int b  = tileid >> 5;
    int t  = tileid & 31;
    int ty = t >> 2, tx = t & 3;
    int tid = threadIdx.x;
    int py  = tid >> 4, pxl = tid & 15;
    int y0g = ty*8 + py, x0g = tx*16 + pxl;

    u64 w01[25], w23[25];
    {
        const float* base = g_W2 + (size_t)b*CO*4096 + y0g*64 + x0g;
        float s0 = 0.f, s1 = 0.f, s2 = 0.f, s3 = 0.f;
#pragma unroll
        for (int k = 0; k < 25; k++) {
            float e0 = __expf(base[(k*4 + 0)*4096]); s0 += e0;
            float e1 = __expf(base[(k*4 + 1)*4096]); s1 += e1;
            w01[k] = pk(e0, e1);
            float e2 = __expf(base[(k*4 + 2)*4096]); s2 += e2;
            float e3 = __expf(base[(k*4 + 3)*4096]); s3 += e3;
            w23[k] = pk(e2, e3);
        }
        u64 i01 = pk(1.0f/s0, 1.0f/s1);
        u64 i23 = pk(1.0f/s2, 1.0f/s3);
#pragma unroll
        for (int k = 0; k < 25; k++) {
            MUL2(w01[k], w01[k], i01);
            MUL2(w23[k], w23[k], i23);
        }
    }

    int cbase = cq*32;
    int ybase = ty*8 - 2, xbase = tx*16 - 2;
    for (int c0 = 0; c0 < 32; c0 += 4) {
        __syncthreads();
        for (int k = tid; k < 960; k += 128) {
            int c = k / 240, p = k - c*240, r = p / 20, cl = p - r*20;
            int y = ybase + r, x = xbase + cl;
            float v = 0.f;
            if ((unsigned)y < 64u && (unsigned)x < 64u)
                v = X[((b*C + cbase + c0 + c)*64 + y)*64 + x];
            xs[c*240 + r*20 + cl] = v;
        }
        __syncthreads();
#pragma unroll
        for (int c = 0; c < 4; c++) {
            u64 a01 = 0ull, a23 = 0ull;
            const float* xp = &xs[c*240 + py*20 + pxl];
#pragma unroll
            for (int i = 0; i < 5; i++)
#pragma unroll
                for (int j = 0; j < 5; j++) {
                    float xv = xp[i*20 + j];
                    u64 xx = pk(xv, xv);
                    int kk = i*5 + j;
                    FMA2(a01, w01[kk], xx);
                    FMA2(a23, w23[kk], xx);
                }
            int ch = cbase + c0 + c;
            size_t ob = ((size_t)(b*C + ch)*HO + 2*y0g)*WO + 2*x0g;
            float2 top = upk(a01), bot = upk(a23);
            *(float2*)&out[ob]      = top;
            *(float2*)&out[ob + WO] = bot;
        }
    }
}

// ---------------------------------------------------------------------------
extern "C" void kernel_launch(void* const* d_in, const int* in_sizes, int n_in,
                              void* d_out, int out_size) {
    const float* X      = (const float*)d_in[0];
    const float* comp_w = (const float*)d_in[1];
    const float* comp_g = (const float*)d_in[2];
    const float* comp_b = (const float*)d_in[3];
    const float* enc_w  = (const float*)d_in[4];
    const float* enc_g  = (const float*)d_in[5];
    const float* enc_b  = (const float*)d_in[6];
    float* out = (float*)d_out;

    k0_prep  <<<252, 256>>>(comp_w, comp_g, enc_w, enc_g);
    k1_comp  <<<256, 256>>>(X, comp_b);
    k2_enc   <<<256, 256>>>(enc_b);
    k3_carafe<<<512, 128>>>(X, out);
}